// round 15
// baseline (speedup 1.0000x reference)
#include <cuda_runtime.h>
#include <cuda_fp16.h>

#define W_DIM 1024
#define F_DIM 512
#define NBC   8
#define BCSTRIDE 524288   // 512*1024
#define SCL2     0.06375871886660017f       // (1/sqrt(512)) * log2(e)

__device__ __half g_P [NBC * F_DIM * W_DIM]; // projection fp16, [bc][g][w] (V source)
__device__ __half g_QT[NBC * F_DIM * W_DIM]; // roped Q==K, TRANSPOSED fp16 [bc][w][h]
__device__ __half g_A [NBC * F_DIM * W_DIM]; // attn out TRANSPOSED fp16 [bc][w][h]
__device__ __half g_XT[NBC * F_DIM * W_DIM]; // x transposed fp16 [bc][w][h]
__device__ __half g_Wq[2 * F_DIM * F_DIM];   // fp16 wq
__device__ __half g_Wo[2 * F_DIM * F_DIM];   // fp16 wo

// ---------------------------------------------------------------------------
// helpers
// ---------------------------------------------------------------------------
__device__ __forceinline__ void cp_async16(void* smem_dst, const void* gsrc) {
    unsigned sdst = (unsigned)__cvta_generic_to_shared(smem_dst);
    asm volatile("cp.async.ca.shared.global [%0], [%1], 16;\n" :: "r"(sdst), "l"(gsrc));
}
#define CP_COMMIT() asm volatile("cp.async.commit_group;\n" ::)
#define CP_WAIT2()  asm volatile("cp.async.wait_group 2;\n" ::)
#define CP_WAIT1()  asm volatile("cp.async.wait_group 1;\n" ::)
#define CP_WAIT0()  asm volatile("cp.async.wait_group 0;\n" ::)

__device__ __forceinline__ void mma_f16(float c[4], unsigned a0, unsigned a1,
                                        unsigned a2, unsigned a3,
                                        unsigned b0, unsigned b1) {
    asm volatile("mma.sync.aligned.m16n8k16.row.col.f32.f16.f16.f32 "
                 "{%0,%1,%2,%3},{%4,%5,%6,%7},{%8,%9},{%0,%1,%2,%3};"
                 : "+f"(c[0]), "+f"(c[1]), "+f"(c[2]), "+f"(c[3])
                 : "r"(a0), "r"(a1), "r"(a2), "r"(a3), "r"(b0), "r"(b1));
}
__device__ __forceinline__ void ldsm4(unsigned& r0, unsigned& r1, unsigned& r2,
                                      unsigned& r3, unsigned addr) {
    asm volatile("ldmatrix.sync.aligned.m8n8.x4.shared.b16 {%0,%1,%2,%3}, [%4];"
                 : "=r"(r0), "=r"(r1), "=r"(r2), "=r"(r3) : "r"(addr));
}
__device__ __forceinline__ unsigned h2u(__half2 h) {
    return *reinterpret_cast<unsigned*>(&h);
}

// ---------------------------------------------------------------------------
// prep: round weights to fp16
// ---------------------------------------------------------------------------
__global__ void prepw_kernel(const float* __restrict__ wq, const float* __restrict__ wo) {
    int i = blockIdx.x * 256 + threadIdx.x;
    g_Wq[i] = __float2half_rn(wq[i]);
    g_Wo[i] = __float2half_rn(wo[i]);
}

// ---------------------------------------------------------------------------
// transpose x[bc][h][w] -> g_XT[bc][w][h], fp16
// ---------------------------------------------------------------------------
__global__ void transpose_kernel(const float* __restrict__ x) {
    __shared__ float t[32][33];
    const int bc = blockIdx.z;
    const int w0 = blockIdx.x * 32, h0 = blockIdx.y * 32;
    const int tx = threadIdx.x, ty = threadIdx.y;
    const float* xb = x + (size_t)bc * BCSTRIDE;
#pragma unroll
    for (int i = 0; i < 4; i++)
        t[ty + 8 * i][tx] = xb[(size_t)(h0 + ty + 8 * i) * W_DIM + w0 + tx];
    __syncthreads();
    __half* xt = g_XT + (size_t)bc * BCSTRIDE;
#pragma unroll
    for (int i = 0; i < 4; i++)
        xt[(size_t)(w0 + ty + 8 * i) * F_DIM + h0 + tx] = __float2half_rn(t[tx][ty + 8 * i]);
}

// ---------------------------------------------------------------------------
// fp16 tensor-core GEMM, 4-stage cp.async pipeline + BATCHED ldsm (MLP 6).
// mode 0: A=g_Wq, B=g_XT -> g_P (fp16) + g_QT (roped, transposed, fp16)
// mode 1: A=g_Wo, B=g_A  -> Op (fp32)
// ---------------------------------------------------------------------------
__global__ __launch_bounds__(256, 2) void gemm_tc(float* __restrict__ Op,
                                                  const float* __restrict__ fp,
                                                  int mode) {
    extern __shared__ __half smh[];
    float2* csT = (float2*)(smh + 40960);   // mode 0 only

    const int bc = blockIdx.z;
    const __half* Wb = (mode == 0 ? g_Wq : g_Wo) + (size_t)(bc & 1) * (F_DIM * F_DIM);
    const __half* Xb = (mode == 0 ? g_XT : g_A) + (size_t)bc * BCSTRIDE;

    const int g0 = blockIdx.y * 128;
    const int w0 = blockIdx.x * 128;
    const int tid = threadIdx.x;
    const int warp = tid >> 5, lane = tid & 31;
    const int wm = warp >> 1, wn = warp & 1;
    const int gid = lane >> 2, tg = lane & 3;

    const unsigned smemB = (unsigned)__cvta_generic_to_shared(smh);
    const int mI = lane >> 3, rI = lane & 7;
    const unsigned ldoff = (unsigned)((((mI & 1) * 8) + rI) * 80 + (mI >> 1) * 16);

    const int lrow = tid >> 2, lgc = tid & 3;

    // prologue: prefetch K-steps 0 and 1 into stages 0,1
#pragma unroll
    for (int s = 0; s < 2; s++) {
        __half* An = smh + s * 10240;
        __half* Bn = An + 5120;
        const int k0 = s * 32;
#pragma unroll
        for (int j = 0; j < 2; j++) {
            int row = lrow + 64 * j;
            cp_async16(&An[row * 40 + lgc * 8], &Wb[(size_t)(g0 + row) * F_DIM + k0 + lgc * 8]);
            cp_async16(&Bn[row * 40 + lgc * 8], &Xb[(size_t)(w0 + row) * F_DIM + k0 + lgc * 8]);
        }
        CP_COMMIT();
    }

    if (mode == 0) {
        for (int t = tid; t < 2048; t += 256) {
            int wl = t >> 4, j = t & 15;
            float sv, cv;
            sincosf((float)(w0 + wl) * fp[j], &sv, &cv);
            csT[t] = make_float2(cv, sv);
        }
    }

    float acc[2][8][4];
#pragma unroll
    for (int mf = 0; mf < 2; mf++)
#pragma unroll
        for (int nt = 0; nt < 8; nt++)
#pragma unroll
            for (int j = 0; j < 4; j++) acc[mf][nt][j] = 0.f;

    for (int t = 0; t < 16; t++) {
        if (t < 14) {
            const int k0 = (t + 2) * 32;
            __half* An = smh + ((t + 2) & 3) * 10240;
            __half* Bn = An + 5120;
#pragma unroll
            for (int j = 0; j < 2; j++) {
                int row = lrow + 64 * j;
                cp_async16(&An[row * 40 + lgc * 8], &Wb[(size_t)(g0 + row) * F_DIM + k0 + lgc * 8]);
                cp_async16(&Bn[row * 40 + lgc * 8], &Xb[(size_t)(w0 + row) * F_DIM + k0 + lgc * 8]);
            }
            CP_COMMIT();
            CP_WAIT2();
        } else if (t == 14) {
            CP_WAIT1();
        } else {
            CP_WAIT0();
        }
        __syncthreads();

        const unsigned AbB = smemB + (unsigned)((t & 3) * 20480);
        const unsigned BbB = AbB + 10240u;
#pragma unroll
        for (int c = 0; c < 2; c++) {
            // batched loads: 2 A + 4 B ldsm issued back-to-back (MLP 6)
            unsigned a[2][4], b[4][4];
            ldsm4(a[0][0], a[0][1], a[0][2], a[0][3],
                  AbB + (unsigned)(wm * 2560) + ldoff + c * 32);
            ldsm4(a[1][0], a[1][1], a[1][2], a[1][3],
                  AbB + (unsigned)(wm * 2560 + 1280) + ldoff + c * 32);
#pragma unroll
            for (int g = 0; g < 4; g++)
                ldsm4(b[g][0], b[g][1], b[g][2], b[g][3],
                      BbB + (unsigned)(wn * 5120 + g * 1280) + ldoff + c * 32);
#pragma unroll
            for (int g = 0; g < 4; g++) {
                mma_f16(acc[0][2 * g],     a[0][0], a[0][1], a[0][2], a[0][3], b[g][0], b[g][2]);
                mma_f16(acc[0][2 * g + 1], a[0][0], a[0][1], a[0][2], a[0][3], b[g][1], b[g][3]);
                mma_f16(acc[1][2 * g],     a[1][0], a[1][1], a[1][2], a[1][3], b[g][0], b[g][2]);
                mma_f16(acc[1][2 * g + 1], a[1][0], a[1][1], a[1][2], a[1][3], b[g][1], b[g][3]);
            }
        }
    }

    if (mode == 1) {
#pragma unroll
        for (int mf = 0; mf < 2; mf++) {
            const int rA = wm * 32 + mf * 16 + gid;
            const int rB = rA + 8;
#pragma unroll
            for (int nt = 0; nt < 8; nt++) {
                const int col = w0 + wn * 64 + nt * 8 + 2 * tg;
                float* dA = &Op[(size_t)bc * BCSTRIDE + (size_t)(g0 + rA) * W_DIM + col];
                float* dB = &Op[(size_t)bc * BCSTRIDE + (size_t)(g0 + rB) * W_DIM + col];
                *(float2*)dA = make_float2(acc[mf][nt][0], acc[mf][nt][1]);
                *(float2*)dB = make_float2(acc[mf][nt][2], acc[mf][nt][3]);
            }
        }
    } else {
        // fused RoPE epilogue; pair partner row (r^1) sits at lane^4. fp16 out.
        __half* Pb  = g_P  + (size_t)bc * BCSTRIDE;
        __half* QTb = g_QT + (size_t)bc * BCSTRIDE;
#pragma unroll
        for (int mf = 0; mf < 2; mf++) {
            const int rA = wm * 32 + mf * 16 + gid;
            const int rB = rA + 8;
            const int hdA = rA & 63, hdB = rB & 63;
            const float sgn = (gid & 1) ? 1.f : -1.f;
#pragma unroll
            for (int nt = 0; nt < 8; nt++) {
                float c0 = acc[mf][nt][0], c1 = acc[mf][nt][1];
                float c2 = acc[mf][nt][2], c3 = acc[mf][nt][3];
                float p0 = __shfl_xor_sync(0xffffffffu, c0, 4);
                float p1 = __shfl_xor_sync(0xffffffffu, c1, 4);
                float p2 = __shfl_xor_sync(0xffffffffu, c2, 4);
                float p3 = __shfl_xor_sync(0xffffffffu, c3, 4);
                const int cl = wn * 64 + nt * 8 + 2 * tg;
                float qa0 = c0, qa1 = c1, qb0 = c2, qb1 = c3;
                if (hdA < 32) {
                    const int j = hdA >> 1;
                    float2 cs0 = csT[cl * 16 + j];
                    float2 cs1 = csT[(cl + 1) * 16 + j];
                    qa0 = c0 * cs0.x + sgn * p0 * cs0.y;
                    qa1 = c1 * cs1.x + sgn * p1 * cs1.y;
                }
                if (hdB < 32) {
                    const int j = hdB >> 1;
                    float2 cs0 = csT[cl * 16 + j];
                    float2 cs1 = csT[(cl + 1) * 16 + j];
                    qb0 = c2 * cs0.x + sgn * p2 * cs0.y;
                    qb1 = c3 * cs1.x + sgn * p3 * cs1.y;
                }
                const int col = w0 + cl;
                *(__half2*)&Pb[(size_t)(g0 + rA) * W_DIM + col] = __floats2half2_rn(c0, c1);
                *(__half2*)&Pb[(size_t)(g0 + rB) * W_DIM + col] = __floats2half2_rn(c2, c3);
                QTb[(size_t)col * F_DIM + g0 + rA]       = __float2half_rn(qa0);
                QTb[(size_t)(col + 1) * F_DIM + g0 + rA] = __float2half_rn(qa1);
                QTb[(size_t)col * F_DIM + g0 + rB]       = __float2half_rn(qb0);
                QTb[(size_t)(col + 1) * F_DIM + g0 + rB] = __float2half_rn(qb1);
            }
        }
    }
}

// ---------------------------------------------------------------------------
// Flash attention: fp16 mma, register-resident P, 4-stage K/V pipeline,
// BATCHED ldsm (MLP 4). smem = 92160 B -> 2 CTA/SM.
// ---------------------------------------------------------------------------
__global__ __launch_bounds__(256, 2) void attn_kernel() {
    extern __shared__ __half smh[];
    __half* Qt = smh;                                   // [128][72] prologue only

    const int tid = threadIdx.x, warp = tid >> 5, lane = tid & 31;
    const int gid = lane >> 2, tg = lane & 3;
    const int q0  = blockIdx.x * 128;
    const int bcn = blockIdx.y;
    const int bc  = bcn >> 3, nh = bcn & 7;

    const __half* QTb = g_QT + (size_t)bc * BCSTRIDE + nh * 64;                 // [w][64]
    const __half* Pb  = g_P  + (size_t)bc * BCSTRIDE + (size_t)nh * 64 * W_DIM; // [d][w]

    const unsigned smemB = (unsigned)__cvta_generic_to_shared(smh);
    const unsigned QtB = smemB;

    const int mI = lane >> 3, rI = lane & 7;
    const unsigned ldoff = (unsigned)((((mI & 1) * 8) + rI) * 144 + (mI >> 1) * 16);

    const int lrow = tid >> 3, lgc = tid & 7;

    // prologue: prefetch KV tiles 0,1 into stages 0,1
#pragma unroll
    for (int s = 0; s < 2; s++) {
        __half* Ks = smh + 9216 + s * 9216;
        __half* Vs = Ks + 4608;
        const int k0 = s * 64;
#pragma unroll
        for (int j = 0; j < 2; j++) {
            int row = lrow + 32 * j;
            cp_async16(&Ks[row * 72 + lgc * 8], &QTb[(size_t)(k0 + row) * F_DIM + lgc * 8]);
            cp_async16(&Vs[row * 72 + lgc * 8], &Pb[(size_t)row * W_DIM + k0 + lgc * 8]);
        }
        CP_COMMIT();
    }

    // ---- stage Q tile [q][72] fp16, pre-scaled by SCL2 in fp32 ----
#pragma unroll
    for (int j = 0; j < 4; j++) {
        int i = tid + 256 * j;
        int row = i >> 3, gc = i & 7;
        uint4 v = *(const uint4*)&QTb[(size_t)(q0 + row) * F_DIM + gc * 8];
        __half2* h = reinterpret_cast<__half2*>(&v);
#pragma unroll
        for (int t = 0; t < 4; t++) {
            float2 f = __half22float2(h[t]);
            h[t] = __floats2half2_rn(f.x * SCL2, f.y * SCL2);
        }
        *(uint4*)&Qt[row * 72 + gc * 8] = v;
    }
    __syncthreads();

    // Q a-fragments resident
    unsigned qa[4][4];
#pragma unroll
    for (int c = 0; c < 4; c++)
        ldsm4(qa[c][0], qa[c][1], qa[c][2], qa[c][3],
              QtB + (unsigned)(warp * 16 * 144) + ldoff + c * 32);

    const unsigned ONES = 0x3C003C00u;   // half2(1, 1)
    float o[8][4];
#pragma unroll
    for (int nt = 0; nt < 8; nt++)
#pragma unroll
        for (int j = 0; j < 4; j++) o[nt][j] = 0.f;
    float lacc[4] = {0.f, 0.f, 0.f, 0.f};

    for (int kt = 0; kt < 16; kt++) {
        if (kt < 14) {
            const int kn = (kt + 2) * 64;
            __half* Ks = smh + 9216 + ((kt + 2) & 3) * 9216;
            __half* Vs = Ks + 4608;
#pragma unroll
            for (int j = 0; j < 2; j++) {
                int row = lrow + 32 * j;
                cp_async16(&Ks[row * 72 + lgc * 8], &QTb[(size_t)(kn + row) * F_DIM + lgc * 8]);
                cp_async16(&Vs[row * 72 + lgc * 8], &Pb[(size_t)row * W_DIM + kn + lgc * 8]);
            }
            CP_COMMIT();
            CP_WAIT2();
        } else if (kt == 14) {
            CP_WAIT1();
        } else {
            CP_WAIT0();
        }
        __syncthreads();

        const unsigned KtB = smemB + 18432u + (unsigned)((kt & 3) * 18432);
        const unsigned VtB = KtB + 9216u;

        // ---- S = (Q*scale) K^T, batched K ldsm per g (MLP 4) ----
        float s[8][4];
#pragma unroll
        for (int nt = 0; nt < 8; nt++)
#pragma unroll
            for (int j = 0; j < 4; j++) s[nt][j] = 0.f;
#pragma unroll
        for (int g = 0; g < 4; g++) {
            const unsigned kb = KtB + (unsigned)(g * 2304) + ldoff;
            unsigned b[4][4];
#pragma unroll
            for (int c = 0; c < 4; c++)
                ldsm4(b[c][0], b[c][1], b[c][2], b[c][3], kb + c * 32);
#pragma unroll
            for (int c = 0; c < 4; c++) {
                mma_f16(s[2 * g],     qa[c][0], qa[c][1], qa[c][2], qa[c][3], b[c][0], b[c][2]);
                mma_f16(s[2 * g + 1], qa[c][0], qa[c][1], qa[c][2], qa[c][3], b[c][1], b[c][3]);
            }
        }

        // ---- P = 2^S in registers (accumulator frag == A frag layout) ----
        unsigned pe[8][2];
#pragma unroll
        for (int nt = 0; nt < 8; nt++) {
            pe[nt][0] = h2u(h2exp2(__floats2half2_rn(s[nt][0], s[nt][1])));
            pe[nt][1] = h2u(h2exp2(__floats2half2_rn(s[nt][2], s[nt][3])));
        }

        // ---- O += P V ; l += P @ ones — batched V ldsm per kc (MLP 4) ----
#pragma unroll
        for (int kc = 0; kc < 4; kc++) {
            const unsigned pa0 = pe[2 * kc][0],     pa1 = pe[2 * kc][1];
            const unsigned pa2 = pe[2 * kc + 1][0], pa3 = pe[2 * kc + 1][1];
            unsigned v[4][4];
#pragma unroll
            for (int g = 0; g < 4; g++)
                ldsm4(v[g][0], v[g][1], v[g][2], v[g][3],
                      VtB + (unsigned)(g * 2304) + ldoff + kc * 32);
            mma_f16(lacc, pa0, pa1, pa2, pa3, ONES, ONES);
#pragma unroll
            for (int g = 0; g < 4; g++) {
                mma_f16(o[2 * g],     pa0, pa1, pa2, pa3, v[g][0], v[g][2]);
                mma_f16(o[2 * g + 1], pa0, pa1, pa2, pa3, v[g][1], v[g][3]);
            }
        }
    }

    // ---- epilogue: normalize by l (full row sums), write g_A fp16 ----
    float inv0 = 1.f / lacc[0], inv1 = 1.f / lacc[2];
    __half* Ag = g_A + (size_t)bc * BCSTRIDE + nh * 64;
    const int qr = q0 + warp * 16 + gid;
#pragma unroll
    for (int nt = 0; nt < 8; nt++) {
        const int col = nt * 8 + 2 * tg;
        *(__half2*)&Ag[(size_t)qr * F_DIM + col] =
            __floats2half2_rn(o[nt][0] * inv0, o[nt][1] * inv0);
        *(__half2*)&Ag[(size_t)(qr + 8) * F_DIM + col] =
            __floats2half2_rn(o[nt][2] * inv1, o[nt][3] * inv1);
    }
}

// ---------------------------------------------------------------------------
// Launch. Inputs: x, wq, wk, wv, wo, freqs_param (wk/wv dead in reference).
// ---------------------------------------------------------------------------
extern "C" void kernel_launch(void* const* d_in, const int* in_sizes, int n_in,
                              void* d_out, int out_size) {
    (void)in_sizes; (void)n_in; (void)out_size;
    const float* x  = (const float*)d_in[0];
    const float* wq = (const float*)d_in[1];
    const float* wo = (const float*)d_in[4];
    const float* fp = (const float*)d_in[5];
    float* out = (float*)d_out;

    cudaFuncSetAttribute(gemm_tc,     cudaFuncAttributeMaxDynamicSharedMemorySize, 98304);
    cudaFuncSetAttribute(attn_kernel, cudaFuncAttributeMaxDynamicSharedMemorySize, 92160);

    prepw_kernel<<<2048, 256>>>(wq, wo);
    transpose_kernel<<<dim3(32, 16, 8), dim3(32, 8)>>>(x);

    dim3 gg(8, 4, 8);
    gemm_tc<<<gg, 256, 98304>>>(nullptr, fp, 0);     // g_P (fp16) + g_QT (roped, T, fp16)
    attn_kernel<<<dim3(8, 64), 256, 92160>>>();      // pipelined flash attn, batched ldsm
    gemm_tc<<<gg, 256, 81920>>>(out, nullptr, 1);    // out = Wo @ A
}

// round 16
// speedup vs baseline: 1.0314x; 1.0314x over previous
#include <cuda_runtime.h>
#include <cuda_fp16.h>

#define W_DIM 1024
#define F_DIM 512
#define NBC   8
#define BCSTRIDE 524288   // 512*1024
#define SCL2     0.06375871886660017f       // (1/sqrt(512)) * log2(e)

__device__ __half g_P [NBC * F_DIM * W_DIM]; // projection fp16, [bc][g][w] (V source)
__device__ __half g_QT[NBC * F_DIM * W_DIM]; // roped Q==K, TRANSPOSED fp16 [bc][w][h]
__device__ __half g_A [NBC * F_DIM * W_DIM]; // attn out TRANSPOSED fp16 [bc][w][h]
__device__ __half g_XT[NBC * F_DIM * W_DIM]; // x transposed fp16 [bc][w][h]
__device__ __half g_Wq[2 * F_DIM * F_DIM];   // fp16 wq
__device__ __half g_Wo[2 * F_DIM * F_DIM];   // fp16 wo

// ---------------------------------------------------------------------------
// helpers
// ---------------------------------------------------------------------------
__device__ __forceinline__ void cp_async16(void* smem_dst, const void* gsrc) {
    unsigned sdst = (unsigned)__cvta_generic_to_shared(smem_dst);
    asm volatile("cp.async.ca.shared.global [%0], [%1], 16;\n" :: "r"(sdst), "l"(gsrc));
}
#define CP_COMMIT() asm volatile("cp.async.commit_group;\n" ::)
#define CP_WAIT2()  asm volatile("cp.async.wait_group 2;\n" ::)
#define CP_WAIT1()  asm volatile("cp.async.wait_group 1;\n" ::)
#define CP_WAIT0()  asm volatile("cp.async.wait_group 0;\n" ::)

__device__ __forceinline__ void mma_f16(float c[4], unsigned a0, unsigned a1,
                                        unsigned a2, unsigned a3,
                                        unsigned b0, unsigned b1) {
    asm volatile("mma.sync.aligned.m16n8k16.row.col.f32.f16.f16.f32 "
                 "{%0,%1,%2,%3},{%4,%5,%6,%7},{%8,%9},{%0,%1,%2,%3};"
                 : "+f"(c[0]), "+f"(c[1]), "+f"(c[2]), "+f"(c[3])
                 : "r"(a0), "r"(a1), "r"(a2), "r"(a3), "r"(b0), "r"(b1));
}
__device__ __forceinline__ void ldsm4(unsigned& r0, unsigned& r1, unsigned& r2,
                                      unsigned& r3, unsigned addr) {
    asm volatile("ldmatrix.sync.aligned.m8n8.x4.shared.b16 {%0,%1,%2,%3}, [%4];"
                 : "=r"(r0), "=r"(r1), "=r"(r2), "=r"(r3) : "r"(addr));
}
__device__ __forceinline__ unsigned h2u(__half2 h) {
    return *reinterpret_cast<unsigned*>(&h);
}

// ---------------------------------------------------------------------------
// prep: round weights to fp16
// ---------------------------------------------------------------------------
__global__ void prepw_kernel(const float* __restrict__ wq, const float* __restrict__ wo) {
    int i = blockIdx.x * 256 + threadIdx.x;
    g_Wq[i] = __float2half_rn(wq[i]);
    g_Wo[i] = __float2half_rn(wo[i]);
}

// ---------------------------------------------------------------------------
// transpose x[bc][h][w] -> g_XT[bc][w][h], fp16
// ---------------------------------------------------------------------------
__global__ void transpose_kernel(const float* __restrict__ x) {
    __shared__ float t[32][33];
    const int bc = blockIdx.z;
    const int w0 = blockIdx.x * 32, h0 = blockIdx.y * 32;
    const int tx = threadIdx.x, ty = threadIdx.y;
    const float* xb = x + (size_t)bc * BCSTRIDE;
#pragma unroll
    for (int i = 0; i < 4; i++)
        t[ty + 8 * i][tx] = xb[(size_t)(h0 + ty + 8 * i) * W_DIM + w0 + tx];
    __syncthreads();
    __half* xt = g_XT + (size_t)bc * BCSTRIDE;
#pragma unroll
    for (int i = 0; i < 4; i++)
        xt[(size_t)(w0 + ty + 8 * i) * F_DIM + h0 + tx] = __float2half_rn(t[tx][ty + 8 * i]);
}

// ---------------------------------------------------------------------------
// fp16 tensor-core GEMM, 4-stage cp.async pipeline (unchanged, passing).
// mode 0: A=g_Wq, B=g_XT -> g_P (fp16) + g_QT (roped, transposed, fp16)
// mode 1: A=g_Wo, B=g_A  -> Op (fp32)
// ---------------------------------------------------------------------------
__global__ __launch_bounds__(256, 2) void gemm_tc(float* __restrict__ Op,
                                                  const float* __restrict__ fp,
                                                  int mode) {
    extern __shared__ __half smh[];
    float2* csT = (float2*)(smh + 40960);   // mode 0 only

    const int bc = blockIdx.z;
    const __half* Wb = (mode == 0 ? g_Wq : g_Wo) + (size_t)(bc & 1) * (F_DIM * F_DIM);
    const __half* Xb = (mode == 0 ? g_XT : g_A) + (size_t)bc * BCSTRIDE;

    const int g0 = blockIdx.y * 128;
    const int w0 = blockIdx.x * 128;
    const int tid = threadIdx.x;
    const int warp = tid >> 5, lane = tid & 31;
    const int wm = warp >> 1, wn = warp & 1;
    const int gid = lane >> 2, tg = lane & 3;

    const unsigned smemB = (unsigned)__cvta_generic_to_shared(smh);
    const int mI = lane >> 3, rI = lane & 7;
    const unsigned ldoff = (unsigned)((((mI & 1) * 8) + rI) * 80 + (mI >> 1) * 16);

    const int lrow = tid >> 2, lgc = tid & 3;

#pragma unroll
    for (int s = 0; s < 2; s++) {
        __half* An = smh + s * 10240;
        __half* Bn = An + 5120;
        const int k0 = s * 32;
#pragma unroll
        for (int j = 0; j < 2; j++) {
            int row = lrow + 64 * j;
            cp_async16(&An[row * 40 + lgc * 8], &Wb[(size_t)(g0 + row) * F_DIM + k0 + lgc * 8]);
            cp_async16(&Bn[row * 40 + lgc * 8], &Xb[(size_t)(w0 + row) * F_DIM + k0 + lgc * 8]);
        }
        CP_COMMIT();
    }

    if (mode == 0) {
        for (int t = tid; t < 2048; t += 256) {
            int wl = t >> 4, j = t & 15;
            float sv, cv;
            sincosf((float)(w0 + wl) * fp[j], &sv, &cv);
            csT[t] = make_float2(cv, sv);
        }
    }

    float acc[2][8][4];
#pragma unroll
    for (int mf = 0; mf < 2; mf++)
#pragma unroll
        for (int nt = 0; nt < 8; nt++)
#pragma unroll
            for (int j = 0; j < 4; j++) acc[mf][nt][j] = 0.f;

    for (int t = 0; t < 16; t++) {
        if (t < 14) {
            const int k0 = (t + 2) * 32;
            __half* An = smh + ((t + 2) & 3) * 10240;
            __half* Bn = An + 5120;
#pragma unroll
            for (int j = 0; j < 2; j++) {
                int row = lrow + 64 * j;
                cp_async16(&An[row * 40 + lgc * 8], &Wb[(size_t)(g0 + row) * F_DIM + k0 + lgc * 8]);
                cp_async16(&Bn[row * 40 + lgc * 8], &Xb[(size_t)(w0 + row) * F_DIM + k0 + lgc * 8]);
            }
            CP_COMMIT();
            CP_WAIT2();
        } else if (t == 14) {
            CP_WAIT1();
        } else {
            CP_WAIT0();
        }
        __syncthreads();

        const unsigned AbB = smemB + (unsigned)((t & 3) * 20480);
        const unsigned BbB = AbB + 10240u;
#pragma unroll
        for (int c = 0; c < 2; c++) {
            unsigned a[2][4], b[4][4];
            ldsm4(a[0][0], a[0][1], a[0][2], a[0][3],
                  AbB + (unsigned)(wm * 2560) + ldoff + c * 32);
            ldsm4(a[1][0], a[1][1], a[1][2], a[1][3],
                  AbB + (unsigned)(wm * 2560 + 1280) + ldoff + c * 32);
#pragma unroll
            for (int g = 0; g < 4; g++)
                ldsm4(b[g][0], b[g][1], b[g][2], b[g][3],
                      BbB + (unsigned)(wn * 5120 + g * 1280) + ldoff + c * 32);
#pragma unroll
            for (int g = 0; g < 4; g++) {
                mma_f16(acc[0][2 * g],     a[0][0], a[0][1], a[0][2], a[0][3], b[g][0], b[g][2]);
                mma_f16(acc[0][2 * g + 1], a[0][0], a[0][1], a[0][2], a[0][3], b[g][1], b[g][3]);
                mma_f16(acc[1][2 * g],     a[1][0], a[1][1], a[1][2], a[1][3], b[g][0], b[g][2]);
                mma_f16(acc[1][2 * g + 1], a[1][0], a[1][1], a[1][2], a[1][3], b[g][1], b[g][3]);
            }
        }
    }

    if (mode == 1) {
#pragma unroll
        for (int mf = 0; mf < 2; mf++) {
            const int rA = wm * 32 + mf * 16 + gid;
            const int rB = rA + 8;
#pragma unroll
            for (int nt = 0; nt < 8; nt++) {
                const int col = w0 + wn * 64 + nt * 8 + 2 * tg;
                float* dA = &Op[(size_t)bc * BCSTRIDE + (size_t)(g0 + rA) * W_DIM + col];
                float* dB = &Op[(size_t)bc * BCSTRIDE + (size_t)(g0 + rB) * W_DIM + col];
                *(float2*)dA = make_float2(acc[mf][nt][0], acc[mf][nt][1]);
                *(float2*)dB = make_float2(acc[mf][nt][2], acc[mf][nt][3]);
            }
        }
    } else {
        __half* Pb  = g_P  + (size_t)bc * BCSTRIDE;
        __half* QTb = g_QT + (size_t)bc * BCSTRIDE;
#pragma unroll
        for (int mf = 0; mf < 2; mf++) {
            const int rA = wm * 32 + mf * 16 + gid;
            const int rB = rA + 8;
            const int hdA = rA & 63, hdB = rB & 63;
            const float sgn = (gid & 1) ? 1.f : -1.f;
#pragma unroll
            for (int nt = 0; nt < 8; nt++) {
                float c0 = acc[mf][nt][0], c1 = acc[mf][nt][1];
                float c2 = acc[mf][nt][2], c3 = acc[mf][nt][3];
                float p0 = __shfl_xor_sync(0xffffffffu, c0, 4);
                float p1 = __shfl_xor_sync(0xffffffffu, c1, 4);
                float p2 = __shfl_xor_sync(0xffffffffu, c2, 4);
                float p3 = __shfl_xor_sync(0xffffffffu, c3, 4);
                const int cl = wn * 64 + nt * 8 + 2 * tg;
                float qa0 = c0, qa1 = c1, qb0 = c2, qb1 = c3;
                if (hdA < 32) {
                    const int j = hdA >> 1;
                    float2 cs0 = csT[cl * 16 + j];
                    float2 cs1 = csT[(cl + 1) * 16 + j];
                    qa0 = c0 * cs0.x + sgn * p0 * cs0.y;
                    qa1 = c1 * cs1.x + sgn * p1 * cs1.y;
                }
                if (hdB < 32) {
                    const int j = hdB >> 1;
                    float2 cs0 = csT[cl * 16 + j];
                    float2 cs1 = csT[(cl + 1) * 16 + j];
                    qb0 = c2 * cs0.x + sgn * p2 * cs0.y;
                    qb1 = c3 * cs1.x + sgn * p3 * cs1.y;
                }
                const int col = w0 + cl;
                *(__half2*)&Pb[(size_t)(g0 + rA) * W_DIM + col] = __floats2half2_rn(c0, c1);
                *(__half2*)&Pb[(size_t)(g0 + rB) * W_DIM + col] = __floats2half2_rn(c2, c3);
                QTb[(size_t)col * F_DIM + g0 + rA]       = __float2half_rn(qa0);
                QTb[(size_t)(col + 1) * F_DIM + g0 + rA] = __float2half_rn(qa1);
                QTb[(size_t)col * F_DIM + g0 + rB]       = __float2half_rn(qb0);
                QTb[(size_t)(col + 1) * F_DIM + g0 + rB] = __float2half_rn(qb1);
            }
        }
    }
}

// ---------------------------------------------------------------------------
// Flash attention: fp16 mma, register P, 4-stage pipeline. NEW: 4 warps/CTA,
// 32 q-rows per warp (two 16-row m-fragments) — K/V fragments loaded ONCE per
// warp serve both halves, halving smem read traffic per unit of work.
// smem halfs: Qt[128][72]=9216, 4 stages x (Kt[64][72]|Vt[64][72])=36864.
// Total 92160 B -> 2 CTA/SM (8 warps/SM).
// ---------------------------------------------------------------------------
__global__ __launch_bounds__(128) void attn_kernel() {
    extern __shared__ __half smh[];
    __half* Qt = smh;                                   // [128][72]

    const int tid = threadIdx.x, warp = tid >> 5, lane = tid & 31;
    const int gid = lane >> 2, tg = lane & 3;
    const int q0  = blockIdx.x * 128;
    const int bcn = blockIdx.y;
    const int bc  = bcn >> 3, nh = bcn & 7;

    const __half* QTb = g_QT + (size_t)bc * BCSTRIDE + nh * 64;                 // [w][64]
    const __half* Pb  = g_P  + (size_t)bc * BCSTRIDE + (size_t)nh * 64 * W_DIM; // [d][w]

    const unsigned smemB = (unsigned)__cvta_generic_to_shared(smh);
    const unsigned QtB = smemB;

    const int mI = lane >> 3, rI = lane & 7;
    const unsigned ldoff = (unsigned)((((mI & 1) * 8) + rI) * 144 + (mI >> 1) * 16);

    const int lrow = tid >> 3, lgc = tid & 7;   // 128 thr: rows 0..15 (+16j)

    // prologue: prefetch KV tiles 0,1 into stages 0,1
#pragma unroll
    for (int s = 0; s < 2; s++) {
        __half* Ks = smh + 9216 + s * 9216;
        __half* Vs = Ks + 4608;
        const int k0 = s * 64;
#pragma unroll
        for (int j = 0; j < 4; j++) {
            int row = lrow + 16 * j;
            cp_async16(&Ks[row * 72 + lgc * 8], &QTb[(size_t)(k0 + row) * F_DIM + lgc * 8]);
            cp_async16(&Vs[row * 72 + lgc * 8], &Pb[(size_t)row * W_DIM + k0 + lgc * 8]);
        }
        CP_COMMIT();
    }

    // ---- stage Q tile [q][72] fp16, pre-scaled by SCL2 in fp32 ----
#pragma unroll
    for (int j = 0; j < 8; j++) {
        int i = tid + 128 * j;
        int row = i >> 3, gc = i & 7;
        uint4 v = *(const uint4*)&QTb[(size_t)(q0 + row) * F_DIM + gc * 8];
        __half2* h = reinterpret_cast<__half2*>(&v);
#pragma unroll
        for (int t = 0; t < 4; t++) {
            float2 f = __half22float2(h[t]);
            h[t] = __floats2half2_rn(f.x * SCL2, f.y * SCL2);
        }
        *(uint4*)&Qt[row * 72 + gc * 8] = v;
    }
    __syncthreads();

    // Q a-fragments resident: two 16-row halves x 4 k-chunks
    unsigned qa[2][4][4];
#pragma unroll
    for (int mf = 0; mf < 2; mf++)
#pragma unroll
        for (int c = 0; c < 4; c++)
            ldsm4(qa[mf][c][0], qa[mf][c][1], qa[mf][c][2], qa[mf][c][3],
                  QtB + (unsigned)((warp * 32 + mf * 16) * 144) + ldoff + c * 32);

    const unsigned ONES = 0x3C003C00u;   // half2(1, 1)
    float o[2][8][4];
#pragma unroll
    for (int mf = 0; mf < 2; mf++)
#pragma unroll
        for (int nt = 0; nt < 8; nt++)
#pragma unroll
            for (int j = 0; j < 4; j++) o[mf][nt][j] = 0.f;
    float lacc[2][4] = {{0.f, 0.f, 0.f, 0.f}, {0.f, 0.f, 0.f, 0.f}};

    for (int kt = 0; kt < 16; kt++) {
        if (kt < 14) {
            const int kn = (kt + 2) * 64;
            __half* Ks = smh + 9216 + ((kt + 2) & 3) * 9216;
            __half* Vs = Ks + 4608;
#pragma unroll
            for (int j = 0; j < 4; j++) {
                int row = lrow + 16 * j;
                cp_async16(&Ks[row * 72 + lgc * 8], &QTb[(size_t)(kn + row) * F_DIM + lgc * 8]);
                cp_async16(&Vs[row * 72 + lgc * 8], &Pb[(size_t)row * W_DIM + kn + lgc * 8]);
            }
            CP_COMMIT();
            CP_WAIT2();
        } else if (kt == 14) {
            CP_WAIT1();
        } else {
            CP_WAIT0();
        }
        __syncthreads();

        const unsigned KtB = smemB + 18432u + (unsigned)((kt & 3) * 18432);
        const unsigned VtB = KtB + 9216u;

        // ---- S = (Q*scale) K^T for BOTH 16-row halves off ONE K-frag load ----
        unsigned pe[2][8][2];
#pragma unroll
        for (int g = 0; g < 4; g++) {
            const unsigned kb = KtB + (unsigned)(g * 2304) + ldoff;
            unsigned b[4][4];
#pragma unroll
            for (int c = 0; c < 4; c++)
                ldsm4(b[c][0], b[c][1], b[c][2], b[c][3], kb + c * 32);
            float s0[4] = {0.f, 0.f, 0.f, 0.f}, s1[4] = {0.f, 0.f, 0.f, 0.f};
            float s2[4] = {0.f, 0.f, 0.f, 0.f}, s3[4] = {0.f, 0.f, 0.f, 0.f};
#pragma unroll
            for (int c = 0; c < 4; c++) {
                mma_f16(s0, qa[0][c][0], qa[0][c][1], qa[0][c][2], qa[0][c][3], b[c][0], b[c][2]);
                mma_f16(s1, qa[0][c][0], qa[0][c][1], qa[0][c][2], qa[0][c][3], b[c][1], b[c][3]);
                mma_f16(s2, qa[1][c][0], qa[1][c][1], qa[1][c][2], qa[1][c][3], b[c][0], b[c][2]);
                mma_f16(s3, qa[1][c][0], qa[1][c][1], qa[1][c][2], qa[1][c][3], b[c][1], b[c][3]);
            }
            pe[0][2 * g][0]     = h2u(h2exp2(__floats2half2_rn(s0[0], s0[1])));
            pe[0][2 * g][1]     = h2u(h2exp2(__floats2half2_rn(s0[2], s0[3])));
            pe[0][2 * g + 1][0] = h2u(h2exp2(__floats2half2_rn(s1[0], s1[1])));
            pe[0][2 * g + 1][1] = h2u(h2exp2(__floats2half2_rn(s1[2], s1[3])));
            pe[1][2 * g][0]     = h2u(h2exp2(__floats2half2_rn(s2[0], s2[1])));
            pe[1][2 * g][1]     = h2u(h2exp2(__floats2half2_rn(s2[2], s2[3])));
            pe[1][2 * g + 1][0] = h2u(h2exp2(__floats2half2_rn(s3[0], s3[1])));
            pe[1][2 * g + 1][1] = h2u(h2exp2(__floats2half2_rn(s3[2], s3[3])));
        }

        // ---- O += P V ; l += P @ ones — ONE V-frag load serves both halves ----
#pragma unroll
        for (int kc = 0; kc < 4; kc++) {
            unsigned v[4][4];
#pragma unroll
            for (int g = 0; g < 4; g++)
                ldsm4(v[g][0], v[g][1], v[g][2], v[g][3],
                      VtB + (unsigned)(g * 2304) + ldoff + kc * 32);
#pragma unroll
            for (int mf = 0; mf < 2; mf++) {
                const unsigned pa0 = pe[mf][2 * kc][0],     pa1 = pe[mf][2 * kc][1];
                const unsigned pa2 = pe[mf][2 * kc + 1][0], pa3 = pe[mf][2 * kc + 1][1];
                mma_f16(lacc[mf], pa0, pa1, pa2, pa3, ONES, ONES);
#pragma unroll
                for (int g = 0; g < 4; g++) {
                    mma_f16(o[mf][2 * g],     pa0, pa1, pa2, pa3, v[g][0], v[g][2]);
                    mma_f16(o[mf][2 * g + 1], pa0, pa1, pa2, pa3, v[g][1], v[g][3]);
                }
            }
        }
    }

    // ---- epilogue: normalize by l (full row sums), write g_A fp16 ----
    __half* Ag = g_A + (size_t)bc * BCSTRIDE + nh * 64;
#pragma unroll
    for (int mf = 0; mf < 2; mf++) {
        float inv0 = 1.f / lacc[mf][0], inv1 = 1.f / lacc[mf][2];
        const int qr = q0 + warp * 32 + mf * 16 + gid;
#pragma unroll
        for (int nt = 0; nt < 8; nt++) {
            const int col = nt * 8 + 2 * tg;
            *(__half2*)&Ag[(size_t)qr * F_DIM + col] =
                __floats2half2_rn(o[mf][nt][0] * inv0, o[mf][nt][1] * inv0);
            *(__half2*)&Ag[(size_t)(qr + 8) * F_DIM + col] =
                __floats2half2_rn(o[mf][nt][2] * inv1, o[mf][nt][3] * inv1);
        }
    }
}

// ---------------------------------------------------------------------------
// Launch. Inputs: x, wq, wk, wv, wo, freqs_param (wk/wv dead in reference).
// ---------------------------------------------------------------------------
extern "C" void kernel_launch(void* const* d_in, const int* in_sizes, int n_in,
                              void* d_out, int out_size) {
    (void)in_sizes; (void)n_in; (void)out_size;
    const float* x  = (const float*)d_in[0];
    const float* wq = (const float*)d_in[1];
    const float* wo = (const float*)d_in[4];
    const float* fp = (const float*)d_in[5];
    float* out = (float*)d_out;

    cudaFuncSetAttribute(gemm_tc,     cudaFuncAttributeMaxDynamicSharedMemorySize, 98304);
    cudaFuncSetAttribute(attn_kernel, cudaFuncAttributeMaxDynamicSharedMemorySize, 92160);

    prepw_kernel<<<2048, 256>>>(wq, wo);
    transpose_kernel<<<dim3(32, 16, 8), dim3(32, 8)>>>(x);

    dim3 gg(8, 4, 8);
    gemm_tc<<<gg, 256, 98304>>>(nullptr, fp, 0);     // g_P (fp16) + g_QT (roped, T, fp16)
    attn_kernel<<<dim3(8, 64), 128, 92160>>>();      // 32 q-rows/warp flash attn
    gemm_tc<<<gg, 256, 81920>>>(out, nullptr, 1);    // out = Wo @ A
}